// round 1
// baseline (speedup 1.0000x reference)
#include <cuda_runtime.h>
#include <cstdint>
#include <cstddef>

// Problem constants (fixed by the reference)
#define NBATCH 4
#define LQ     8192
#define M_TOK  (NBATCH * LQ)      // 32768 query tokens
#define LIN    21760              // 128^2 + 64^2 + 32^2 + 16^2
#define M_VAL  (NBATCH * LIN)     // 87040 value rows
#define DMODEL 256
#define DFF    1024
#define NHEAD  8
#define HDIM   32

// ---------------------------------------------------------------------------
// Scratch (allocation-free: __device__ globals)
// ---------------------------------------------------------------------------
__device__ float g_value  [(size_t)M_VAL * DMODEL];   // 89.1 MB
__device__ float g_off    [(size_t)M_TOK * DMODEL];   // 33.5 MB
__device__ float g_logits [(size_t)M_TOK * 128];      // 16.8 MB
__device__ float g_attnpre[(size_t)M_TOK * DMODEL];   // 33.5 MB
__device__ float g_attnout[(size_t)M_TOK * DMODEL];   // 33.5 MB
__device__ float g_x      [(size_t)M_TOK * DMODEL];   // 33.5 MB
__device__ float g_h1     [(size_t)M_TOK * DFF];      // 134 MB
__device__ float g_ffn    [(size_t)M_TOK * DMODEL];   // 33.5 MB

// ---------------------------------------------------------------------------
// Generic fp32 SGEMM: C[M,N] = op(A)[M,K] @ B[K,N] + bias, tiled 128x128x8.
// MODE 0: C = A@B + bias
// MODE 1: C = A@B + bias, then zero rows where mask[row] != 0
// MODE 2: C = (A + A2)@B + bias          (A2 = query_pos)
// MODE 3: C = relu(A@B + bias)
// Requires M % 128 == 0, N % 128 == 0, K % 8 == 0.
// ---------------------------------------------------------------------------
template <int MODE>
__global__ __launch_bounds__(256, 2)
void sgemm_kernel(const float* __restrict__ A, const float* __restrict__ A2,
                  const float* __restrict__ B, const float* __restrict__ bias,
                  const unsigned char* __restrict__ mask,
                  float* __restrict__ C, int M, int N, int K)
{
    __shared__ float As[8][128];
    __shared__ float Bs[8][128];

    const int t = threadIdx.x;
    const int rowBase = blockIdx.y * 128;
    const int colBase = blockIdx.x * 128;

    const int arow = t >> 1;          // 0..127
    const int acol = (t & 1) * 4;     // 0 or 4
    const int brow = t >> 5;          // 0..7
    const int bcol = (t & 31) * 4;    // 0..124
    const int ty = t >> 4;            // 0..15
    const int tx = t & 15;            // 0..15

    float acc[8][8];
    #pragma unroll
    for (int i = 0; i < 8; i++)
        #pragma unroll
        for (int j = 0; j < 8; j++) acc[i][j] = 0.f;

    const float* Aptr  = A  + (size_t)(rowBase + arow) * K + acol;
    const float* A2ptr = (MODE == 2) ? (A2 + (size_t)(rowBase + arow) * K + acol) : nullptr;
    const float* Bptr  = B + (size_t)brow * N + colBase + bcol;

    for (int k0 = 0; k0 < K; k0 += 8) {
        float4 av = *(const float4*)(Aptr + k0);
        if (MODE == 2) {
            float4 a2 = *(const float4*)(A2ptr + k0);
            av.x += a2.x; av.y += a2.y; av.z += a2.z; av.w += a2.w;
        }
        float4 bv = *(const float4*)(Bptr + (size_t)k0 * N);

        As[acol + 0][arow] = av.x;
        As[acol + 1][arow] = av.y;
        As[acol + 2][arow] = av.z;
        As[acol + 3][arow] = av.w;
        *(float4*)&Bs[brow][bcol] = bv;
        __syncthreads();

        #pragma unroll
        for (int kk = 0; kk < 8; kk++) {
            float4 a0 = *(const float4*)&As[kk][ty * 8];
            float4 a1 = *(const float4*)&As[kk][ty * 8 + 4];
            float4 b0 = *(const float4*)&Bs[kk][tx * 8];
            float4 b1 = *(const float4*)&Bs[kk][tx * 8 + 4];
            float a[8] = {a0.x, a0.y, a0.z, a0.w, a1.x, a1.y, a1.z, a1.w};
            float b[8] = {b0.x, b0.y, b0.z, b0.w, b1.x, b1.y, b1.z, b1.w};
            #pragma unroll
            for (int i = 0; i < 8; i++)
                #pragma unroll
                for (int j = 0; j < 8; j++)
                    acc[i][j] = fmaf(a[i], b[j], acc[i][j]);
        }
        __syncthreads();
    }

    #pragma unroll
    for (int i = 0; i < 8; i++) {
        const int r = rowBase + ty * 8 + i;
        const bool mz = (MODE == 1) ? (mask[r] != 0) : false;
        float* Crow = C + (size_t)r * N + colBase + tx * 8;
        #pragma unroll
        for (int j = 0; j < 8; j += 4) {
            float4 v;
            v.x = acc[i][j + 0] + __ldg(bias + colBase + tx * 8 + j + 0);
            v.y = acc[i][j + 1] + __ldg(bias + colBase + tx * 8 + j + 1);
            v.z = acc[i][j + 2] + __ldg(bias + colBase + tx * 8 + j + 2);
            v.w = acc[i][j + 3] + __ldg(bias + colBase + tx * 8 + j + 3);
            if (MODE == 3) {
                v.x = fmaxf(v.x, 0.f); v.y = fmaxf(v.y, 0.f);
                v.z = fmaxf(v.z, 0.f); v.w = fmaxf(v.w, 0.f);
            }
            if (MODE == 1 && mz) { v.x = 0.f; v.y = 0.f; v.z = 0.f; v.w = 0.f; }
            *(float4*)(Crow + j) = v;
        }
    }
}

// ---------------------------------------------------------------------------
// Deformable sampling + in-warp softmax.
// One block per token (256 threads = 8 warps), one warp per head,
// one lane per head-dim element. Output: g_attnpre[m, h*32 + lane].
// ---------------------------------------------------------------------------
__global__ __launch_bounds__(256)
void sample_kernel(const float* __restrict__ off,     // [M_TOK, 256]
                   const float* __restrict__ logits,  // [M_TOK, 128]
                   const float* __restrict__ refp,    // [M_TOK, 4, 2]
                   const float* __restrict__ value,   // [NBATCH, LIN, 256]
                   float* __restrict__ out)           // [M_TOK, 256]
{
    const unsigned FULL = 0xffffffffu;
    const int m = blockIdx.x;
    const int n = m >> 13;                 // m / LQ
    const int h = threadIdx.x >> 5;
    const int lane = threadIdx.x & 31;

    const float* offq = off + (size_t)m * 256 + h * 32;
    const float* logq = logits + (size_t)m * 128 + h * 16;
    const float* refq = refp + (size_t)m * 8;
    const float* vb = value + (size_t)n * LIN * 256 + h * 32 + lane;

    // Per-lane raw data; broadcast later via shuffles.
    const float ov = offq[lane];                       // 32 offset scalars
    const float rv = (lane < 8) ? refq[lane] : 0.f;    // 8 ref scalars
    float lg = (lane < 16) ? logq[lane] : -1e30f;

    // softmax over 16 logits (full-warp reductions; lanes 16..31 neutral)
    float mx = lg;
    #pragma unroll
    for (int s = 16; s >= 1; s >>= 1)
        mx = fmaxf(mx, __shfl_xor_sync(FULL, mx, s));
    float e = (lane < 16) ? expf(lg - mx) : 0.f;
    float sum = e;
    #pragma unroll
    for (int s = 16; s >= 1; s >>= 1)
        sum += __shfl_xor_sync(FULL, sum, s);
    const float wsm = e / sum;

    const int   Wl[4]     = {128, 64, 32, 16};
    const int   starts[4] = {0, 16384, 20480, 21504};

    float acc = 0.f;
    #pragma unroll
    for (int l = 0; l < 4; l++) {
        const float rx = __shfl_sync(FULL, rv, l * 2);
        const float ry = __shfl_sync(FULL, rv, l * 2 + 1);
        const float Wf = (float)Wl[l];
        const int   W  = Wl[l];
        const int   base = starts[l];
        #pragma unroll
        for (int p = 0; p < 4; p++) {
            const float ox = __shfl_sync(FULL, ov, (l * 4 + p) * 2);
            const float oy = __shfl_sync(FULL, ov, (l * 4 + p) * 2 + 1);
            const float aw = __shfl_sync(FULL, wsm, l * 4 + p);
            // loc = ref + off/[W,H]; pixel = loc*W - 0.5 = ref*W + off - 0.5
            const float x = fmaf(rx, Wf, ox) - 0.5f;
            const float y = fmaf(ry, Wf, oy) - 0.5f;
            const float x0 = floorf(x), y0 = floorf(y);
            const float dx = x - x0, dy = y - y0;
            float pts = 0.f;
            #pragma unroll
            for (int cy = 0; cy < 2; cy++) {
                #pragma unroll
                for (int cx = 0; cx < 2; cx++) {
                    const float fx = x0 + (float)cx;
                    const float fy = y0 + (float)cy;
                    const float w = (cx ? dx : 1.f - dx) * (cy ? dy : 1.f - dy);
                    if (fx >= 0.f && fx <= Wf - 1.f && fy >= 0.f && fy <= Wf - 1.f) {
                        const int idx = base + (int)fy * W + (int)fx;
                        pts = fmaf(w, __ldg(vb + (size_t)idx * 256), pts);
                    }
                }
            }
            acc = fmaf(aw, pts, acc);
        }
    }
    out[(size_t)m * 256 + h * 32 + lane] = acc;
}

// ---------------------------------------------------------------------------
// LayerNorm(a + b) with gamma/beta. One warp per row (D=256, 8 elems/lane).
// ---------------------------------------------------------------------------
__global__ __launch_bounds__(256)
void ln_kernel(const float* __restrict__ a, const float* __restrict__ b,
               const float* __restrict__ gamma, const float* __restrict__ beta,
               float* __restrict__ out)
{
    const unsigned FULL = 0xffffffffu;
    const int warp = threadIdx.x >> 5;
    const int lane = threadIdx.x & 31;
    const int row = blockIdx.x * 8 + warp;

    const float* ar = a + (size_t)row * 256;
    const float* br = b + (size_t)row * 256;

    float v[8];
    float s = 0.f;
    #pragma unroll
    for (int i = 0; i < 8; i++) {
        v[i] = ar[lane + i * 32] + br[lane + i * 32];
        s += v[i];
    }
    #pragma unroll
    for (int o = 16; o >= 1; o >>= 1) s += __shfl_xor_sync(FULL, s, o);
    const float mean = s * (1.f / 256.f);

    float q = 0.f;
    #pragma unroll
    for (int i = 0; i < 8; i++) { const float d = v[i] - mean; q = fmaf(d, d, q); }
    #pragma unroll
    for (int o = 16; o >= 1; o >>= 1) q += __shfl_xor_sync(FULL, q, o);
    const float inv = rsqrtf(q * (1.f / 256.f) + 1e-5f);

    float* orow = out + (size_t)row * 256;
    #pragma unroll
    for (int i = 0; i < 8; i++) {
        const int c = lane + i * 32;
        orow[c] = (v[i] - mean) * inv * __ldg(gamma + c) + __ldg(beta + c);
    }
}

// ---------------------------------------------------------------------------
// Launch
// ---------------------------------------------------------------------------
extern "C" void kernel_launch(void* const* d_in, const int* in_sizes, int n_in,
                              void* d_out, int out_size)
{
    const float* tgt    = (const float*)d_in[0];
    const float* qpos   = (const float*)d_in[1];
    const float* refp   = (const float*)d_in[2];
    const float* src    = (const float*)d_in[3];
    // d_in[4] = src_spatial_shapes (int64)  -> compile-time constants, ignored
    // d_in[5] = level_start_index  (int64)  -> compile-time constants, ignored
    const unsigned char* mask = (const unsigned char*)d_in[6];
    const float* W_off  = (const float*)d_in[7];
    const float* b_off  = (const float*)d_in[8];
    const float* W_attn = (const float*)d_in[9];
    const float* b_attn = (const float*)d_in[10];
    const float* W_val  = (const float*)d_in[11];
    const float* b_val  = (const float*)d_in[12];
    const float* W_out  = (const float*)d_in[13];
    const float* b_out  = (const float*)d_in[14];
    const float* ln1_g  = (const float*)d_in[15];
    const float* ln1_b  = (const float*)d_in[16];
    const float* W_fc1  = (const float*)d_in[17];
    const float* b_fc1  = (const float*)d_in[18];
    const float* W_fc2  = (const float*)d_in[19];
    const float* b_fc2  = (const float*)d_in[20];
    const float* ln2_g  = (const float*)d_in[21];
    const float* ln2_b  = (const float*)d_in[22];
    float* out = (float*)d_out;

    float *value, *offb, *logitsb, *attnpre, *attnout, *xb, *h1b, *ffnb;
    cudaGetSymbolAddress((void**)&value,   g_value);
    cudaGetSymbolAddress((void**)&offb,    g_off);
    cudaGetSymbolAddress((void**)&logitsb, g_logits);
    cudaGetSymbolAddress((void**)&attnpre, g_attnpre);
    cudaGetSymbolAddress((void**)&attnout, g_attnout);
    cudaGetSymbolAddress((void**)&xb,      g_x);
    cudaGetSymbolAddress((void**)&h1b,     g_h1);
    cudaGetSymbolAddress((void**)&ffnb,    g_ffn);

    const dim3 blk(256);

    // 1) value = mask0(src @ W_val + b_val)          [87040 x 256]
    sgemm_kernel<1><<<dim3(DMODEL / 128, M_VAL / 128), blk>>>(
        src, nullptr, W_val, b_val, mask, value, M_VAL, DMODEL, DMODEL);

    // 2) off = (tgt + qpos) @ W_off + b_off          [32768 x 256]
    sgemm_kernel<2><<<dim3(DMODEL / 128, M_TOK / 128), blk>>>(
        tgt, qpos, W_off, b_off, nullptr, offb, M_TOK, DMODEL, DMODEL);

    // 3) logits = (tgt + qpos) @ W_attn + b_attn     [32768 x 128]
    sgemm_kernel<2><<<dim3(1, M_TOK / 128), blk>>>(
        tgt, qpos, W_attn, b_attn, nullptr, logitsb, M_TOK, 128, DMODEL);

    // 4) deformable sampling (+softmax)              [32768 x 256]
    sample_kernel<<<M_TOK, blk>>>(offb, logitsb, refp, value, attnpre);

    // 5) attn_out = attnpre @ W_out + b_out
    sgemm_kernel<0><<<dim3(DMODEL / 128, M_TOK / 128), blk>>>(
        attnpre, nullptr, W_out, b_out, nullptr, attnout, M_TOK, DMODEL, DMODEL);

    // 6) x = LN(tgt + attn_out)
    ln_kernel<<<M_TOK / 8, blk>>>(tgt, attnout, ln1_g, ln1_b, xb);

    // 7) h1 = relu(x @ W_fc1 + b_fc1)                [32768 x 1024]
    sgemm_kernel<3><<<dim3(DFF / 128, M_TOK / 128), blk>>>(
        xb, nullptr, W_fc1, b_fc1, nullptr, h1b, M_TOK, DFF, DMODEL);

    // 8) ffn = h1 @ W_fc2 + b_fc2                    [32768 x 256], K=1024
    sgemm_kernel<0><<<dim3(DMODEL / 128, M_TOK / 128), blk>>>(
        h1b, nullptr, W_fc2, b_fc2, nullptr, ffnb, M_TOK, DMODEL, DFF);

    // 9) out = LN(x + ffn)
    ln_kernel<<<M_TOK / 8, blk>>>(xb, ffnb, ln2_g, ln2_b, out);
}

// round 4
// speedup vs baseline: 1.5216x; 1.5216x over previous
#include <cuda_runtime.h>
#include <cuda_bf16.h>
#include <cstdint>
#include <cstddef>

// Problem constants (fixed by the reference)
#define NBATCH 4
#define LQ     8192
#define M_TOK  (NBATCH * LQ)      // 32768 query tokens
#define LIN    21760              // 128^2+64^2+32^2+16^2
#define M_VAL  (NBATCH * LIN)     // 87040 value rows
#define DMODEL 256
#define DFF    1024

// ---------------------------------------------------------------------------
// Scratch (__device__ globals; allocation-free)
// ---------------------------------------------------------------------------
// bf16 "triple" activations: layout [M, 3K] = [hi | hi | lo]
__device__ __align__(128) __nv_bfloat16 g_src3[(size_t)M_VAL * 768];
__device__ __align__(128) __nv_bfloat16 g_q3  [(size_t)M_TOK * 768];
__device__ __align__(128) __nv_bfloat16 g_ap3 [(size_t)M_TOK * 768];
__device__ __align__(128) __nv_bfloat16 g_x3  [(size_t)M_TOK * 768];
__device__ __align__(128) __nv_bfloat16 g_h13 [(size_t)M_TOK * 3072];
// bf16 "triple" weights, transposed: [N, 3K] = [hi | lo | hi]
__device__ __align__(128) __nv_bfloat16 g_wval3 [256 * 768];
__device__ __align__(128) __nv_bfloat16 g_woff3 [256 * 768];
__device__ __align__(128) __nv_bfloat16 g_wattn3[128 * 768];
__device__ __align__(128) __nv_bfloat16 g_wout3 [256 * 768];
__device__ __align__(128) __nv_bfloat16 g_wfc13 [1024 * 768];
__device__ __align__(128) __nv_bfloat16 g_wfc23 [(size_t)256 * 3072];
// fp32 intermediates
__device__ __align__(128) float g_value  [(size_t)M_VAL * DMODEL];
__device__ __align__(128) float g_off    [(size_t)M_TOK * DMODEL];
__device__ __align__(128) float g_logits [(size_t)M_TOK * 128];
__device__ __align__(128) float g_attnout[(size_t)M_TOK * DMODEL];
__device__ __align__(128) float g_x      [(size_t)M_TOK * DMODEL];
__device__ __align__(128) float g_ffn    [(size_t)M_TOK * DMODEL];

// ---------------------------------------------------------------------------
// Helpers
// ---------------------------------------------------------------------------
__device__ __forceinline__ uint32_t smem_u32(const void* p) {
    uint32_t a;
    asm("{ .reg .u64 t; cvta.to.shared.u64 t, %1; cvt.u32.u64 %0, t; }" : "=r"(a) : "l"(p));
    return a;
}
__device__ __forceinline__ void cp_async16(uint32_t dst, const void* src) {
    asm volatile("cp.async.cg.shared.global [%0], [%1], 16;" :: "r"(dst), "l"(src));
}
__device__ __forceinline__ void cp_commit() { asm volatile("cp.async.commit_group;" ::: "memory"); }
template <int N>
__device__ __forceinline__ void cp_wait() {
    asm volatile("cp.async.wait_group %0;" :: "n"(N) : "memory");
}
__device__ __forceinline__ uint32_t sw128(uint32_t off) { return off ^ ((off >> 3) & 0x70); }

__device__ __forceinline__ void ldm_x4(uint32_t& r0, uint32_t& r1, uint32_t& r2, uint32_t& r3,
                                       uint32_t addr) {
    asm volatile("ldmatrix.sync.aligned.m8n8.x4.shared.b16 {%0,%1,%2,%3}, [%4];"
                 : "=r"(r0), "=r"(r1), "=r"(r2), "=r"(r3) : "r"(addr));
}
__device__ __forceinline__ void mma16816(float* d, const uint32_t* a, uint32_t b0, uint32_t b1) {
    asm volatile("mma.sync.aligned.m16n8k16.row.col.f32.bf16.bf16.f32 "
                 "{%0,%1,%2,%3}, {%4,%5,%6,%7}, {%8,%9}, {%0,%1,%2,%3};"
                 : "+f"(d[0]), "+f"(d[1]), "+f"(d[2]), "+f"(d[3])
                 : "r"(a[0]), "r"(a[1]), "r"(a[2]), "r"(a[3]), "r"(b0), "r"(b1));
}

// ---------------------------------------------------------------------------
// bf16 GEMM via mma.sync: C[M, Nfull] = A3[M, Kp] @ Bt3[N, Kp]^T (+epilogue)
// CTA tile 128x128, K-chunk 32, 8 warps (2x4), warp tile 64x32.
// ---------------------------------------------------------------------------
template <bool RELU, bool MASK, bool OUTF32, bool OUTTRI>
__global__ __launch_bounds__(256, 2)
void gemm_mma(const __nv_bfloat16* __restrict__ A3,
              const __nv_bfloat16* __restrict__ Bt3,
              const float* __restrict__ bias,
              const unsigned char* __restrict__ mask,
              float* __restrict__ Cf,
              __nv_bfloat16* __restrict__ C3,
              int Kp, int Nfull)
{
    __shared__ __align__(1024) char smem[32768];  // 2 stages x (A 8KB + B 8KB)
    const uint32_t sb = smem_u32(smem);

    const int tid  = threadIdx.x;
    const int wid  = tid >> 5;
    const int lane = tid & 31;
    const int rowBase = blockIdx.x * 128;
    const int colBase = blockIdx.y * 128;
    const int NC = Kp >> 5;

    const int mWarp = (wid >> 2) * 64;   // 0 or 64
    const int nWarp = (wid & 3) * 32;    // 0,32,64,96

    const __nv_bfloat16* Arow = A3 + (size_t)rowBase * Kp;
    const __nv_bfloat16* Brow = Bt3 + (size_t)colBase * Kp;

    float acc[4][4][4];
    #pragma unroll
    for (int i = 0; i < 4; i++)
        #pragma unroll
        for (int j = 0; j < 4; j++)
            #pragma unroll
            for (int k = 0; k < 4; k++) acc[i][j][k] = 0.f;

    // ldmatrix lane-address components (lin offset = row*64 + k*2, sw128 applied)
    const int lmRow = (lane & 7) + ((lane >> 3) & 1) * 8;  // row within 16-row tile
    const int lmK   = ((lane >> 4) & 1) * 8;               // k-half within 16

    // loader: thread handles 4 chunks of A + 4 of B per stage
    const int ldRow = tid >> 2;   // 0..63  -> row pairs: rows = ldRow and ldRow+64
    const int ldC   = tid & 3;    // 16B chunk within 64B row

    auto load_stage = [&](int s, int kc) {
        const uint32_t aB = sb + (uint32_t)s * 16384;
        const uint32_t bB = aB + 8192;
        const __nv_bfloat16* Ac = Arow + (size_t)kc * 32 + ldC * 8;
        const __nv_bfloat16* Bc = Brow + (size_t)kc * 32 + ldC * 8;
        #pragma unroll
        for (int h = 0; h < 2; h++) {
            const int r = ldRow + h * 64;
            cp_async16(aB + sw128((uint32_t)(r * 64 + ldC * 16)), Ac + (size_t)r * Kp);
            cp_async16(bB + sw128((uint32_t)(r * 64 + ldC * 16)), Bc + (size_t)r * Kp);
        }
    };

    load_stage(0, 0);
    cp_commit();

    for (int kc = 0; kc < NC; kc++) {
        const int s = kc & 1;
        if (kc + 1 < NC) { load_stage(s ^ 1, kc + 1); cp_commit(); cp_wait<1>(); }
        else             { cp_wait<0>(); }
        __syncthreads();

        const uint32_t aB = sb + (uint32_t)s * 16384;
        const uint32_t bB = aB + 8192;

        #pragma unroll
        for (int ks = 0; ks < 2; ks++) {
            const int kk = ks * 16 + lmK;
            uint32_t af[4][4];
            #pragma unroll
            for (int mt = 0; mt < 4; mt++) {
                const uint32_t lin = (uint32_t)((mWarp + mt * 16 + lmRow) * 64 + kk * 2);
                ldm_x4(af[mt][0], af[mt][1], af[mt][2], af[mt][3], aB + sw128(lin));
            }
            uint32_t bf_[2][4];
            #pragma unroll
            for (int bg = 0; bg < 2; bg++) {
                const uint32_t lin = (uint32_t)((nWarp + bg * 16 + lmRow) * 64 + kk * 2);
                ldm_x4(bf_[bg][0], bf_[bg][1], bf_[bg][2], bf_[bg][3], bB + sw128(lin));
            }
            #pragma unroll
            for (int mt = 0; mt < 4; mt++)
                #pragma unroll
                for (int nt = 0; nt < 4; nt++) {
                    const int bg = nt >> 1, sel = nt & 1;
                    mma16816(acc[mt][nt], af[mt], bf_[bg][sel], bf_[bg][sel + 2]);
                }
        }
        __syncthreads();
    }

    // Epilogue. Thread holds (row g / g+8, cols tig*2, tig*2+1) per (mt, nt).
    const int g = lane >> 2;
    const int tig = lane & 3;

    #pragma unroll
    for (int mt = 0; mt < 4; mt++) {
        const int r0 = rowBase + mWarp + mt * 16 + g;
        const int r1 = r0 + 8;
        bool mz0 = false, mz1 = false;
        if (MASK) { mz0 = (mask[r0] != 0); mz1 = (mask[r1] != 0); }
        #pragma unroll
        for (int nt = 0; nt < 4; nt++) {
            const int col = colBase + nWarp + nt * 8 + tig * 2;
            const float b0 = __ldg(bias + col);
            const float b1 = __ldg(bias + col + 1);
            float v00 = acc[mt][nt][0] + b0, v01 = acc[mt][nt][1] + b1;
            float v10 = acc[mt][nt][2] + b0, v11 = acc[mt][nt][3] + b1;
            if (RELU) {
                v00 = fmaxf(v00, 0.f); v01 = fmaxf(v01, 0.f);
                v10 = fmaxf(v10, 0.f); v11 = fmaxf(v11, 0.f);
            }
            if (MASK) {
                if (mz0) { v00 = 0.f; v01 = 0.f; }
                if (mz1) { v10 = 0.f; v11 = 0.f; }
            }
            if (OUTF32) {
                *(float2*)(Cf + (size_t)r0 * Nfull + col) = make_float2(v00, v01);
                *(float2*)(Cf + (size_t)r1 * Nfull + col) = make_float2(v10, v11);
            }
            if (OUTTRI) {
                const size_t st = 3 * (size_t)Nfull;
                #pragma unroll
                for (int h = 0; h < 2; h++) {
                    const float a0 = h ? v10 : v00;
                    const float a1 = h ? v11 : v01;
                    const size_t rb = (size_t)(h ? r1 : r0) * st;
                    __nv_bfloat16 h0 = __float2bfloat16(a0);
                    __nv_bfloat16 l0 = __float2bfloat16(a0 - __bfloat162float(h0));
                    __nv_bfloat16 h1 = __float2bfloat16(a1);
                    __nv_bfloat16 l1 = __float2bfloat16(a1 - __bfloat162float(h1));
                    __nv_bfloat162 hh; hh.x = h0; hh.y = h1;
                    __nv_bfloat162 ll; ll.x = l0; ll.y = l1;
                    *(__nv_bfloat162*)(C3 + rb + col) = hh;
                    *(__nv_bfloat162*)(C3 + rb + Nfull + col) = hh;
                    *(__nv_bfloat162*)(C3 + rb + 2 * (size_t)Nfull + col) = ll;
                }
            }
        }
    }
}

// ---------------------------------------------------------------------------
// Split conversions (fp32 -> bf16 hi/lo triples)
// ---------------------------------------------------------------------------
__global__ void split_weight(const float* __restrict__ W, __nv_bfloat16* __restrict__ out,
                             int K, int N)
{
    const int idx = blockIdx.x * blockDim.x + threadIdx.x;
    if (idx >= K * N) return;
    const int k = idx / N, n = idx % N;
    const float w = W[idx];
    const __nv_bfloat16 hi = __float2bfloat16(w);
    const __nv_bfloat16 lo = __float2bfloat16(w - __bfloat162float(hi));
    const size_t base = (size_t)n * 3 * K;
    out[base + k] = hi;                  // seg0: Bh (pairs with Ah)
    out[base + K + k] = lo;              // seg1: Bl (pairs with Ah)
    out[base + 2 * (size_t)K + k] = hi;  // seg2: Bh (pairs with Al)
}

template <bool SUM>
__global__ void split_act(const float* __restrict__ a, const float* __restrict__ b,
                          __nv_bfloat16* __restrict__ out, int K)
{
    const size_t idx = (size_t)blockIdx.x * blockDim.x + threadIdx.x;
    const size_t r = idx / K;
    const int c = (int)(idx % K);
    float v = a[idx];
    if (SUM) v += b[idx];
    const __nv_bfloat16 hi = __float2bfloat16(v);
    const __nv_bfloat16 lo = __float2bfloat16(v - __bfloat162float(hi));
    const size_t base = r * 3 * (size_t)K;
    out[base + c] = hi;                  // seg0: Ah
    out[base + K + c] = hi;              // seg1: Ah
    out[base + 2 * (size_t)K + c] = lo;  // seg2: Al
}

// ---------------------------------------------------------------------------
// Deformable sampling + in-warp softmax; emits bf16 triple output.
// ---------------------------------------------------------------------------
__global__ __launch_bounds__(256)
void sample_kernel(const float* __restrict__ off,     // [M_TOK, 256]
                   const float* __restrict__ logits,  // [M_TOK, 128]
                   const float* __restrict__ refp,    // [M_TOK, 4, 2]
                   const float* __restrict__ value,   // [NBATCH, LIN, 256]
                   __nv_bfloat16* __restrict__ out3)  // [M_TOK, 768]
{
    const unsigned FULL = 0xffffffffu;
    const int m = blockIdx.x;
    const int n = m >> 13;
    const int h = threadIdx.x >> 5;
    const int lane = threadIdx.x & 31;

    const float* offq = off + (size_t)m * 256 + h * 32;
    const float* logq = logits + (size_t)m * 128 + h * 16;
    const float* refq = refp + (size_t)m * 8;
    const float* vb = value + (size_t)n * LIN * 256 + h * 32 + lane;

    const float ov = offq[lane];
    const float rv = (lane < 8) ? refq[lane] : 0.f;
    float lg = (lane < 16) ? logq[lane] : -1e30f;

    float mx = lg;
    #pragma unroll
    for (int s = 16; s >= 1; s >>= 1) mx = fmaxf(mx, __shfl_xor_sync(FULL, mx, s));
    float e = (lane < 16) ? expf(lg - mx) : 0.f;
    float sum = e;
    #pragma unroll
    for (int s = 16; s >= 1; s >>= 1) sum += __shfl_xor_sync(FULL, sum, s);
    const float wsm = e / sum;

    const int Wl[4]     = {128, 64, 32, 16};
    const int starts[4] = {0, 16384, 20480, 21504};

    float acc = 0.f;
    #pragma unroll
    for (int l = 0; l < 4; l++) {
        const float rx = __shfl_sync(FULL, rv, l * 2);
        const float ry = __shfl_sync(FULL, rv, l * 2 + 1);
        const float Wf = (float)Wl[l];
        const int   W  = Wl[l];
        const int   base = starts[l];
        #pragma unroll
        for (int p = 0; p < 4; p++) {
            const float ox = __shfl_sync(FULL, ov, (l * 4 + p) * 2);
            const float oy = __shfl_sync(FULL, ov, (l * 4 + p) * 2 + 1);
            const float aw = __shfl_sync(FULL, wsm, l * 4 + p);
            const float x = fmaf(rx, Wf, ox) - 0.5f;
            const float y = fmaf(ry, Wf, oy) - 0.5f;
            const float x0 = floorf(x), y0 = floorf(y);
            const float dx = x - x0, dy = y - y0;
            float pts = 0.f;
            #pragma unroll
            for (int cy = 0; cy < 2; cy++) {
                #pragma unroll
                for (int cx = 0; cx < 2; cx++) {
                    const float fx = x0 + (float)cx;
                    const float fy = y0 + (float)cy;
                    const float w = (cx ? dx : 1.f - dx) * (cy ? dy : 1.f - dy);
                    if (fx >= 0.f && fx <= Wf - 1.f && fy >= 0.f && fy <= Wf - 1.f) {
                        const int idx = base + (int)fy * W + (int)fx;
                        pts = fmaf(w, __ldg(vb + (size_t)idx * 256), pts);
                    }
                }
            }
            acc = fmaf(aw, pts, acc);
        }
    }
    const __nv_bfloat16 hi = __float2bfloat16(acc);
    const __nv_bfloat16 lo = __float2bfloat16(acc - __bfloat162float(hi));
    const size_t base = (size_t)m * 768;
    const int c = h * 32 + lane;
    out3[base + c] = hi;
    out3[base + 256 + c] = hi;
    out3[base + 512 + c] = lo;
}

// ---------------------------------------------------------------------------
// LayerNorm(a + b); optionally also emits bf16 triple (for fc1 input).
// ---------------------------------------------------------------------------
template <bool TRI>
__global__ __launch_bounds__(256)
void ln_kernel(const float* __restrict__ a, const float* __restrict__ b,
               const float* __restrict__ gamma, const float* __restrict__ beta,
               float* __restrict__ out, __nv_bfloat16* __restrict__ out3)
{
    const unsigned FULL = 0xffffffffu;
    const int warp = threadIdx.x >> 5;
    const int lane = threadIdx.x & 31;
    const int row = blockIdx.x * 8 + warp;

    const float* ar = a + (size_t)row * 256;
    const float* br = b + (size_t)row * 256;

    float v[8];
    float s = 0.f;
    #pragma unroll
    for (int i = 0; i < 8; i++) {
        v[i] = ar[lane + i * 32] + br[lane + i * 32];
        s += v[i];
    }
    #pragma unroll
    for (int o = 16; o >= 1; o >>= 1) s += __shfl_xor_sync(FULL, s, o);
    const float mean = s * (1.f / 256.f);

    float q = 0.f;
    #pragma unroll
    for (int i = 0; i < 8; i++) { const float d = v[i] - mean; q = fmaf(d, d, q); }
    #pragma unroll
    for (int o = 16; o >= 1; o >>= 1) q += __shfl_xor_sync(FULL, q, o);
    const float inv = rsqrtf(q * (1.f / 256.f) + 1e-5f);

    float* orow = out + (size_t)row * 256;
    const size_t tb = (size_t)row * 768;
    #pragma unroll
    for (int i = 0; i < 8; i++) {
        const int c = lane + i * 32;
        const float y = (v[i] - mean) * inv * __ldg(gamma + c) + __ldg(beta + c);
        orow[c] = y;
        if (TRI) {
            const __nv_bfloat16 hi = __float2bfloat16(y);
            const __nv_bfloat16 lo = __float2bfloat16(y - __bfloat162float(hi));
            out3[tb + c] = hi;
            out3[tb + 256 + c] = hi;
            out3[tb + 512 + c] = lo;
        }
    }
}

// ---------------------------------------------------------------------------
// Launch
// ---------------------------------------------------------------------------
extern "C" void kernel_launch(void* const* d_in, const int* in_sizes, int n_in,
                              void* d_out, int out_size)
{
    const float* tgt    = (const float*)d_in[0];
    const float* qpos   = (const float*)d_in[1];
    const float* refp   = (const float*)d_in[2];
    const float* src    = (const float*)d_in[3];
    const unsigned char* mask = (const unsigned char*)d_in[6];
    const float* W_off  = (const float*)d_in[7];
    const float* b_off  = (const float*)d_in[8];
    const float* W_attn = (const float*)d_in[9];
    const float* b_attn = (const float*)d_in[10];
    const float* W_val  = (const float*)d_in[11];
    const float* b_val  = (const float*)d_in[12];
    const float* W_out  = (const float*)d_in[13];
    const float* b_out  = (const float*)d_in[14];
    const float* ln1_g  = (const float*)d_in[15];
    const float* ln1_b  = (const float*)d_in[16];
    const float* W_fc1  = (const float*)d_in[17];
    const float* b_fc1  = (const float*)d_in[18];
    const float* W_fc2  = (const float*)d_in[19];
    const float* b_fc2  = (const float*)d_in[20];
    const float* ln2_g  = (const float*)d_in[21];
    const float* ln2_b  = (const float*)d_in[22];
    float* out = (float*)d_out;

    __nv_bfloat16 *src3, *q3, *ap3, *x3, *h13;
    __nv_bfloat16 *wval3, *woff3, *wattn3, *wout3, *wfc13, *wfc23;
    float *value, *offb, *logitsb, *attnout, *xb, *ffnb;
    cudaGetSymbolAddress((void**)&src3,   g_src3);
    cudaGetSymbolAddress((void**)&q3,     g_q3);
    cudaGetSymbolAddress((void**)&ap3,    g_ap3);
    cudaGetSymbolAddress((void**)&x3,     g_x3);
    cudaGetSymbolAddress((void**)&h13,    g_h13);
    cudaGetSymbolAddress((void**)&wval3,  g_wval3);
    cudaGetSymbolAddress((void**)&woff3,  g_woff3);
    cudaGetSymbolAddress((void**)&wattn3, g_wattn3);
    cudaGetSymbolAddress((void**)&wout3,  g_wout3);
    cudaGetSymbolAddress((void**)&wfc13,  g_wfc13);
    cudaGetSymbolAddress((void**)&wfc23,  g_wfc23);
    cudaGetSymbolAddress((void**)&value,  g_value);
    cudaGetSymbolAddress((void**)&offb,   g_off);
    cudaGetSymbolAddress((void**)&logitsb,g_logits);
    cudaGetSymbolAddress((void**)&attnout,g_attnout);
    cudaGetSymbolAddress((void**)&xb,     g_x);
    cudaGetSymbolAddress((void**)&ffnb,   g_ffn);

    const dim3 blk(256);

    // Weight splits (tiny)
    split_weight<<<(256 * 256 + 255) / 256, blk>>>(W_val,  wval3,  256, 256);
    split_weight<<<(256 * 256 + 255) / 256, blk>>>(W_off,  woff3,  256, 256);
    split_weight<<<(256 * 128 + 255) / 256, blk>>>(W_attn, wattn3, 256, 128);
    split_weight<<<(256 * 256 + 255) / 256, blk>>>(W_out,  wout3,  256, 256);
    split_weight<<<(256 * 1024 + 255) / 256, blk>>>(W_fc1, wfc13,  256, 1024);
    split_weight<<<(1024 * 256 + 255) / 256, blk>>>(W_fc2, wfc23, 1024, 256);

    // Activation splits
    split_act<false><<<M_VAL, blk>>>(src, nullptr, src3, 256);
    split_act<true ><<<M_TOK, blk>>>(tgt, qpos,    q3,   256);

    // 1) value = mask0(src @ W_val + b_val)          [87040 x 256]
    gemm_mma<false, true, true, false><<<dim3(M_VAL / 128, 2), blk>>>(
        src3, wval3, b_val, mask, value, nullptr, 768, 256);

    // 2) off = q @ W_off + b_off                     [32768 x 256]
    gemm_mma<false, false, true, false><<<dim3(M_TOK / 128, 2), blk>>>(
        q3, woff3, b_off, nullptr, offb, nullptr, 768, 256);

    // 3) logits = q @ W_attn + b_attn                [32768 x 128]
    gemm_mma<false, false, true, false><<<dim3(M_TOK / 128, 1), blk>>>(
        q3, wattn3, b_attn, nullptr, logitsb, nullptr, 768, 128);

    // 4) sampling -> attnpre triple                  [32768 x 256]
    sample_kernel<<<M_TOK, blk>>>(offb, logitsb, refp, value, ap3);

    // 5) attn_out = attnpre @ W_out + b_out
    gemm_mma<false, false, true, false><<<dim3(M_TOK / 128, 2), blk>>>(
        ap3, wout3, b_out, nullptr, attnout, nullptr, 768, 256);

    // 6) x = LN(tgt + attn_out)  (also emit x triple)
    ln_kernel<true><<<M_TOK / 8, blk>>>(tgt, attnout, ln1_g, ln1_b, xb, x3);

    // 7) h1 = relu(x @ W_fc1 + b_fc1) -> triple only [32768 x 1024]
    gemm_mma<true, false, false, true><<<dim3(M_TOK / 128, 8), blk>>>(
        x3, wfc13, b_fc1, nullptr, nullptr, h13, 768, 1024);

    // 8) ffn = h1 @ W_fc2 + b_fc2                    [32768 x 256], Kp=3072
    gemm_mma<false, false, true, false><<<dim3(M_TOK / 128, 2), blk>>>(
        h13, wfc23, b_fc2, nullptr, ffnb, nullptr, 3072, 256);

    // 9) out = LN(x + ffn)
    ln_kernel<false><<<M_TOK / 8, blk>>>(xb, ffnb, ln2_g, ln2_b, out, nullptr);
}